// round 13
// baseline (speedup 1.0000x reference)
#include <cuda_runtime.h>
#include <math.h>

// Problem constants
#define Bz 64
#define Hd 512
#define Sl 64
#define Tt 32
#define BH (Bz*Hd)
#define NB 128
#define NT 512

// Output layout
#define OFF_AT 1048576
#define OFF_HF 1179648
#define OFF_CF 1245184
#define OFF_FF 1310720

// ---------------------------------------------------------------------------
// Persistent storage.
__device__ float g_WT0[1536*2048];   // [emb|feed|h0] -> gates0, [k][j]
__device__ float g_WT1[1024*2048];   // [h0n|h1p]     -> gates1, [k][j]
__device__ float g_WoT[1024*512];    // Wout^T: [k(cvec|h1n)][j]
__device__ float g_ctxT[512*4096];   // ctx transposed [h][sb]
__device__ float g_ctxW[4096*512];   // [sb][k] = sum_j ctx[sb][j]*Wa[j][k]
__device__ float g_ctxWo[4096*512];  // [sb][j] = sum_k ctx[sb][k]*Wout[j][k] (k<512)
// Transposed activations [u][b]:
__device__ float g_h0T[Hd*Bz], g_h1T[Hd*Bz], g_feedT[Hd*Bz], g_embT[Hd*Bz];
// Split-K partials [j][b]:
__device__ float g_g0[8][2048*64];
__device__ float g_g1[8][2048*64];
__device__ float g_op[16][512*64];
__device__ float g_opc[512*64];      // attention-half of out GEMM, [j][b]
__device__ unsigned g_arr[NB];       // per-block arrival flags (zero-init)
__device__ unsigned g_bargen = 0u;

__device__ __forceinline__ float sigf(float x){ return 1.0f/(1.0f+__expf(-x)); }

// Distributed-flag grid barrier: no contended atomics. Block k releases its
// own slot; block 0's threads 1..NB-1 each poll one slot, then block 0
// releases g_bargen. Generations are monotonic -> no flag reset needed.
__device__ __forceinline__ void gridbar_to(unsigned target){
    __syncthreads();
    if (blockIdx.x == 0){
        if (threadIdx.x > 0 && threadIdx.x < NB){
            unsigned g;
            do {
                asm volatile("ld.acquire.gpu.global.u32 %0, [%1];"
                             : "=r"(g) : "l"((const unsigned*)&g_arr[threadIdx.x]) : "memory");
            } while (g != target);
        }
        __syncthreads();
        if (threadIdx.x == 0)
            asm volatile("st.release.gpu.global.u32 [%0], %1;"
                         :: "l"(&g_bargen), "r"(target) : "memory");
    } else {
        if (threadIdx.x == 0){
            asm volatile("st.release.gpu.global.u32 [%0], %1;"
                         :: "l"(&g_arr[blockIdx.x]), "r"(target) : "memory");
            unsigned g;
            do {
                asm volatile("ld.acquire.gpu.global.u32 %0, [%1];"
                             : "=r"(g) : "l"((const unsigned*)&g_bargen) : "memory");
            } while (g != target);
        }
        __syncthreads();
    }
}

// Packed fp32x2 FMA helpers (SASS FFMA2; bit-identical to 2x FFMA).
#define FMA2(acc, xx, w) asm("fma.rn.f32x2 %0, %1, %2, %0;" : "+l"(acc) : "l"(xx), "l"(w))
#define BCAST2(xx, xf)   do { unsigned _u = __float_as_uint(xf); \
    asm("mov.b64 %0, {%1, %1};" : "=l"(xx) : "r"(_u)); } while(0)

// ---------------------------------------------------------------------------
// 64b x 128j tile GEMM, 512 threads, 4b x 4j micro-tile via 8 FFMA2/kk.
// x rows [k][b] (pitch xpitch), w rows [k][j] (pitch wpitch). Coalesced LDG,
// double-buffered smem, ONE __syncthreads per chunk.
// ---------------------------------------------------------------------------
template<bool XCG, class FX, class FW>
__device__ __forceinline__ void gemm_tile(float (&a)[4][4], FX fx, FW fw,
        int nch, int xpitch, int wpitch, float* sx, float* sw)
{
    const int tid = threadIdx.x;
    const int bq = tid & 15, kx = tid >> 4;    // x loader
    const int jq = tid & 31, kw = tid >> 5;    // w loader (x2 rows)
    const int tb4 = (tid & 15) << 2, tj4 = (tid >> 4) << 2;
    float4 xv, wv0, wv1;
    unsigned long long acc[4][2] = {{0ull,0ull},{0ull,0ull},{0ull,0ull},{0ull,0ull}};

    {
        const float* xp = fx(0) + kx*xpitch + (bq<<2);
        xv  = XCG ? __ldcg((const float4*)xp) : __ldg((const float4*)xp);
        const float* wp = fw(0);
        wv0 = __ldg((const float4*)(wp + (size_t)kw*wpitch + (jq<<2)));
        wv1 = __ldg((const float4*)(wp + (size_t)(kw+16)*wpitch + (jq<<2)));
        *(float4*)(sx + kx*68 + (bq<<2))        = xv;
        *(float4*)(sw + kw*132 + (jq<<2))       = wv0;
        *(float4*)(sw + (kw+16)*132 + (jq<<2))  = wv1;
    }
    __syncthreads();

    for (int c = 0; c < nch; ++c){
        const bool more = (c+1 < nch);
        if (more){
            const float* xp = fx(c+1) + kx*xpitch + (bq<<2);
            xv  = XCG ? __ldcg((const float4*)xp) : __ldg((const float4*)xp);
            const float* wp = fw(c+1);
            wv0 = __ldg((const float4*)(wp + (size_t)kw*wpitch + (jq<<2)));
            wv1 = __ldg((const float4*)(wp + (size_t)(kw+16)*wpitch + (jq<<2)));
        }
        const float* xb = sx + (c&1)*2176;
        const float* wb = sw + (c&1)*4224;
        #pragma unroll
        for (int kk = 0; kk < 32; ++kk){
            float4 x4 = *(const float4*)(xb + kk*68 + tb4);
            ulonglong2 w2 = *(const ulonglong2*)(wb + kk*132 + tj4);
            unsigned long long xx0, xx1, xx2, xx3;
            BCAST2(xx0, x4.x); FMA2(acc[0][0], xx0, w2.x); FMA2(acc[0][1], xx0, w2.y);
            BCAST2(xx1, x4.y); FMA2(acc[1][0], xx1, w2.x); FMA2(acc[1][1], xx1, w2.y);
            BCAST2(xx2, x4.z); FMA2(acc[2][0], xx2, w2.x); FMA2(acc[2][1], xx2, w2.y);
            BCAST2(xx3, x4.w); FMA2(acc[3][0], xx3, w2.x); FMA2(acc[3][1], xx3, w2.y);
        }
        if (more){
            float* xn = sx + ((c+1)&1)*2176;
            float* wn = sw + ((c+1)&1)*4224;
            *(float4*)(xn + kx*68 + (bq<<2))        = xv;
            *(float4*)(wn + kw*132 + (jq<<2))       = wv0;
            *(float4*)(wn + (kw+16)*132 + (jq<<2))  = wv1;
        }
        __syncthreads();
    }
    #pragma unroll
    for (int r = 0; r < 4; ++r){
        unsigned l0,h0,l1,h1;
        asm("mov.b64 {%0, %1}, %2;" : "=r"(l0), "=r"(h0) : "l"(acc[r][0]));
        asm("mov.b64 {%0, %1}, %2;" : "=r"(l1), "=r"(h1) : "l"(acc[r][1]));
        a[r][0]=__uint_as_float(l0); a[r][1]=__uint_as_float(h0);
        a[r][2]=__uint_as_float(l1); a[r][3]=__uint_as_float(h1);
    }
}

// ---------------------------------------------------------------------------
__global__ __launch_bounds__(NT, 1) void kMain(
    const int*   __restrict__ toks, const float* __restrict__ ctx,
    const float* __restrict__ h0i,  const float* __restrict__ c0i,
    const float* __restrict__ feedi,const float* __restrict__ emb,
    const float* __restrict__ Wih0, const float* __restrict__ Whh0,
    const float* __restrict__ bih0, const float* __restrict__ bhh0,
    const float* __restrict__ Wih1, const float* __restrict__ Whh1,
    const float* __restrict__ bih1, const float* __restrict__ bhh1,
    const float* __restrict__ Wa,   const float* __restrict__ Wout,
    float* __restrict__ dout)
{
    extern __shared__ float smem[];
    float* sx  = smem;                    // 2 x 32 x 68
    float* sw  = smem + 4352;             // 2 x 32 x 132
    float* qs  = smem + 4352 + 8448;      // 512
    float* sSc = qs + 512;                // 64
    float* sAl = sSc + 64;                // 64

    const int blk = blockIdx.x, tid = threadIdx.x;
    const int tb4 = (tid & 15) << 2, tj4 = (tid >> 4) << 2;

    unsigned bgen = *(volatile unsigned*)&g_bargen;

    // ---- per-thread persistent state ----
    float c0reg = 0.f, bs0i=0.f, bs0f=0.f, bs0g=0.f, bs0o=0.f;
    if (tid < 256){
        int elem = blk*256 + tid;         // = u*64 + b
        int u = elem >> 6, b = elem & 63;
        c0reg = c0i[b*Hd + u];
        bs0i = __ldg(bih0+u)      + __ldg(bhh0+u);
        bs0f = __ldg(bih0+512+u)  + __ldg(bhh0+512+u);
        bs0g = __ldg(bih0+1024+u) + __ldg(bhh0+1024+u);
        bs0o = __ldg(bih0+1536+u) + __ldg(bhh0+1536+u);
    }
    float c1reg = 0.f, bs1[4] = {0.f,0.f,0.f,0.f};
    if (blk < Bz){
        c1reg = c0i[BH + blk*Hd + tid];
        #pragma unroll
        for (int g = 0; g < 4; ++g)
            bs1[g] = __ldg(bih1+g*512+tid) + __ldg(bhh1+g*512+tid);
    }

    // ---- init transposed state + emb(t=0) ----
    if (tid < 256){
        int idx = blk*256 + tid;          // = b*512 + u
        int b = idx >> 9, u = idx & 511;
        __stcg(&g_h0T[u*64+b],  h0i[idx]);
        __stcg(&g_h1T[u*64+b],  h0i[BH + idx]);
        __stcg(&g_feedT[u*64+b],feedi[idx]);
        __stcg(&g_embT[u*64+b], __ldg(emb + (size_t)__ldg(toks+b)*512 + u));
    }

    // ---- one-time transposes (weights, ctx) via smem 64x64 tiles ----
    {
        float* ts = sx;
        for (int tl = blk; tl < 1920; tl += NB){
            const float* sp; float* dp;
            int spitch, sk0, srow0, dpitch, dk0, dj0;
            if (tl < 768){
                int kt=tl>>5, jt=tl&31; dk0=kt<<6; dj0=jt<<6; srow0=dj0;
                dp=g_WT0; dpitch=2048;
                if (dk0<1024){ sp=Wih0; spitch=1024; sk0=dk0; }
                else         { sp=Whh0; spitch=512;  sk0=dk0-1024; }
            } else if (tl < 1280){
                int ti=tl-768; int kt=ti>>5, jt=ti&31; dk0=kt<<6; dj0=jt<<6; srow0=dj0;
                dp=g_WT1; dpitch=2048;
                if (dk0<512){ sp=Wih1; spitch=512; sk0=dk0; }
                else        { sp=Whh1; spitch=512; sk0=dk0-512; }
            } else if (tl < 1408){
                int ti=tl-1280; int kt=ti>>3, jt=ti&7; dk0=kt<<6; dj0=jt<<6; srow0=dj0;
                dp=g_WoT; dpitch=512; sp=Wout; spitch=1024; sk0=dk0;
            } else {
                int ti=tl-1408; int kt=ti>>6, jt=ti&63; dk0=kt<<6; dj0=jt<<6; srow0=dj0;
                dp=g_ctxT; dpitch=4096; sp=ctx; spitch=512; sk0=dk0;
            }
            #pragma unroll
            for (int it2=0; it2<2; ++it2){
                int q = it2*512 + tid; int jr=q>>4, kc4=(q&15)<<2;
                float4 v = __ldg((const float4*)(sp + (size_t)(srow0+jr)*spitch + sk0 + kc4));
                ts[(kc4+0)*65+jr]=v.x; ts[(kc4+1)*65+jr]=v.y;
                ts[(kc4+2)*65+jr]=v.z; ts[(kc4+3)*65+jr]=v.w;
            }
            __syncthreads();
            #pragma unroll
            for (int it2=0; it2<2; ++it2){
                int q = it2*512 + tid; int kr=q>>4, jc4=(q&15)<<2;
                float4 v = make_float4(ts[kr*65+jc4], ts[kr*65+jc4+1],
                                       ts[kr*65+jc4+2], ts[kr*65+jc4+3]);
                *(float4*)(dp + (size_t)(dk0+kr)*dpitch + dj0 + jc4) = v;
            }
            __syncthreads();
        }
    }
    gridbar_to(++bgen);

    // ---- one-time ctxW (Wa) and ctxWo (Wout cvec-half) ----
    for (int it = 0; it < 4; ++it){
        int job = it*NB + blk;            // 0..511
        int half = job >> 8;              // 0: ctxW, 1: ctxWo
        int j2 = job & 255;
        int sb0 = (j2 >> 2) << 6;
        int j0v = (j2 & 3) << 7;
        float a[4][4] = {};
        auto fx = [&](int c) -> const float* { return g_ctxT + (size_t)(c<<5)*4096 + sb0; };
        auto fw = [&](int c) -> const float* {
            return (half ? (const float*)g_WoT : Wa) + (size_t)(c<<5)*512 + j0v;
        };
        gemm_tile<false>(a, fx, fw, 16, 4096, 512, sx, sw);
        float* dst = half ? g_ctxWo : g_ctxW;
        #pragma unroll
        for (int bi = 0; bi < 4; ++bi)
            *(float4*)&dst[(size_t)(sb0 + tb4 + bi)*512 + j0v + tj4]
                = make_float4(a[bi][0],a[bi][1],a[bi][2],a[bi][3]);
    }
    gridbar_to(++bgen);

    // ---- time loop ----
    for (int t = 0; t < Tt; ++t){

        // Phase A1: gates0 partials. 16 j-tiles(128) x 8 K-splits (K=192).
        {
            const int ks = blk >> 4, j0v = (blk & 15) << 7;
            const int kbase = ks * 192;
            float a[4][4] = {};
            auto fx = [&](int c) -> const float* {
                int kg = kbase + (c<<5);
                if (kg < 512)  return g_embT + kg*64;
                if (kg < 1024) return g_feedT + (kg-512)*64;
                return g_h0T + (kg-1024)*64;
            };
            auto fw = [&](int c) -> const float* {
                return g_WT0 + (size_t)(kbase + (c<<5))*2048 + j0v;
            };
            gemm_tile<true>(a, fx, fw, 6, 64, 2048, sx, sw);
            float* gp = g_g0[ks];
            #pragma unroll
            for (int jj = 0; jj < 4; ++jj)
                __stcg((float4*)&gp[(j0v + tj4 + jj)*64 + tb4],
                       make_float4(a[0][jj],a[1][jj],a[2][jj],a[3][jj]));
        }
        gridbar_to(++bgen);

        // Phase A2: combine + LSTM cell 0
        if (tid < 256){
            int elem = blk*256 + tid;
            int u = elem >> 6, b = elem & 63;
            float vi=bs0i, vf=bs0f, vg=bs0g, vo=bs0o;
            #pragma unroll
            for (int ks = 0; ks < 8; ++ks){
                const float* G = g_g0[ks];
                vi += __ldcg(&G[(u       )*64 + b]);
                vf += __ldcg(&G[(512+u)  *64 + b]);
                vg += __ldcg(&G[(1024+u) *64 + b]);
                vo += __ldcg(&G[(1536+u) *64 + b]);
            }
            float cn = sigf(vf)*c0reg + sigf(vi)*tanhf(vg);
            float hn = sigf(vo)*tanhf(cn);
            c0reg = cn;
            __stcg(&g_h0T[elem], hn);
            if (t == Tt-1){ dout[OFF_HF + b*Hd + u] = hn; dout[OFF_CF + b*Hd + u] = cn; }
        }
        gridbar_to(++bgen);

        // Phase B1: gates1 partials. 16 j-tiles x 8 K-splits (K=128).
        {
            const int ks = blk >> 4, j0v = (blk & 15) << 7;
            const int kbase = ks << 7;
            float a[4][4] = {};
            auto fx = [&](int c) -> const float* {
                int kg = kbase + (c<<5);
                return (kg < 512) ? g_h0T + kg*64 : g_h1T + (kg-512)*64;
            };
            auto fw = [&](int c) -> const float* {
                return g_WT1 + (size_t)(kbase + (c<<5))*2048 + j0v;
            };
            gemm_tile<true>(a, fx, fw, 4, 64, 2048, sx, sw);
            float* gp = g_g1[ks];
            #pragma unroll
            for (int jj = 0; jj < 4; ++jj)
                __stcg((float4*)&gp[(j0v + tj4 + jj)*64 + tb4],
                       make_float4(a[0][jj],a[1][jj],a[2][jj],a[3][jj]));
        }
        gridbar_to(++bgen);

        // Phase S (blocks 0..63): cell 1 + scores + softmax + attention-half out.
        if (blk < Bz){
            const int b = blk, u = tid;
            float vi=bs1[0], vf=bs1[1], vg=bs1[2], vo=bs1[3];
            #pragma unroll
            for (int ks = 0; ks < 8; ++ks){
                const float* G = g_g1[ks];
                vi += __ldcg(&G[(u       )*64 + b]);
                vf += __ldcg(&G[(512+u)  *64 + b]);
                vg += __ldcg(&G[(1024+u) *64 + b]);
                vo += __ldcg(&G[(1536+u) *64 + b]);
            }
            float cn = sigf(vf)*c1reg + sigf(vi)*tanhf(vg);
            float hn = sigf(vo)*tanhf(cn);
            c1reg = cn;
            qs[u] = hn;
            __stcg(&g_h1T[u*64 + b], hn);
            if (t == Tt-1){ dout[OFF_HF + BH + b*Hd + u] = hn; dout[OFF_CF + BH + b*Hd + u] = cn; }
            __syncthreads();
            // scores: warp wp -> s = wp*4..+3, lanes over k
            const int wp = tid >> 5, lane = tid & 31;
            #pragma unroll
            for (int si = 0; si < 4; ++si){
                const int s = wp*4 + si;
                const float* cw = g_ctxW + ((size_t)(s*Bz + b) << 9) + lane;
                float acc = 0.f;
                #pragma unroll
                for (int i = 0; i < 16; ++i) acc = fmaf(qs[lane + (i<<5)], __ldg(cw + (i<<5)), acc);
                #pragma unroll
                for (int o = 16; o; o >>= 1) acc += __shfl_xor_sync(0xffffffffu, acc, o);
                if (lane == 0) sSc[s] = acc;
            }
            __syncthreads();
            if (tid < 32){
                float v0 = sSc[tid], v1 = sSc[tid+32];
                float m = fmaxf(v0, v1);
                #pragma unroll
                for (int o = 16; o; o >>= 1) m = fmaxf(m, __shfl_xor_sync(0xffffffffu, m, o));
                float e0 = __expf(v0 - m), e1 = __expf(v1 - m);
                float ssum = e0 + e1;
                #pragma unroll
                for (int o = 16; o; o >>= 1) ssum += __shfl_xor_sync(0xffffffffu, ssum, o);
                float inv = 1.f/ssum;
                sAl[tid] = e0*inv;  sAl[tid+32] = e1*inv;
                dout[OFF_AT + t*Bz*Sl + b*Sl + tid]      = e0*inv;
                dout[OFF_AT + t*Bz*Sl + b*Sl + tid + 32] = e1*inv;
            }
            __syncthreads();
            {   // out_c[b][j] = sum_s al[s] * ctxWo[s*64+b][j], j = tid
                float acc = 0.f;
                const float* cw = g_ctxWo + ((size_t)b << 9) + tid;
                #pragma unroll 8
                for (int s2 = 0; s2 < Sl; ++s2)
                    acc = fmaf(sAl[s2], __ldg(cw + ((size_t)s2 << 15)), acc);
                __stcg(&g_opc[tid*64 + b], acc);
            }
        }
        gridbar_to(++bgen);

        // Phase O1: h1n-half of out GEMM. 4 j-tiles(128) x 16 K-splits (K=32).
        if (blk < 64){
            const int ks = blk >> 2, j0v = (blk & 3) << 7;
            const int kbase = ks << 5;
            float a[4][4] = {};
            auto fx = [&](int) -> const float* { return g_h1T + kbase*64; };
            auto fw = [&](int) -> const float* {
                return g_WoT + (size_t)(512 + kbase)*512 + j0v;
            };
            gemm_tile<true>(a, fx, fw, 1, 64, 512, sx, sw);
            float* gp = g_op[ks];
            #pragma unroll
            for (int jj = 0; jj < 4; ++jj)
                __stcg((float4*)&gp[(j0v + tj4 + jj)*64 + tb4],
                       make_float4(a[0][jj],a[1][jj],a[2][jj],a[3][jj]));
        }
        gridbar_to(++bgen);

        // Phase O2: combine 16 partials + attention half + tanh -> feedT,
        // outputs[t], feedf; gather emb for step t+1.
        if (tid < 256){
            int elem = blk*256 + tid;     // = h*64 + b
            int h = elem >> 6, b = elem & 63;
            float s = __ldcg(&g_opc[elem]);
            #pragma unroll
            for (int ks = 0; ks < 16; ++ks) s += __ldcg(&g_op[ks][elem]);
            float o = tanhf(s);
            __stcg(&g_feedT[elem], o);
            dout[t*BH + b*Hd + h] = o;
            if (t == Tt-1) dout[OFF_FF + b*Hd + h] = o;
            if (t+1 < Tt){
                int b2 = elem >> 9, k2 = elem & 511;
                float ev = __ldg(emb + (size_t)__ldg(toks + (t+1)*Bz + b2)*512 + k2);
                __stcg(&g_embT[k2*64 + b2], ev);
            }
        }
        gridbar_to(++bgen);
    }
}

// ---------------------------------------------------------------------------
extern "C" void kernel_launch(void* const* d_in, const int* in_sizes, int n_in,
                              void* d_out, int out_size)
{
    const int*   toks = (const int*)  d_in[0];
    // d_in[1] = src (unused by the reference computation)
    const float* ctx  = (const float*)d_in[2];
    const float* h0   = (const float*)d_in[3];
    const float* c0   = (const float*)d_in[4];
    const float* feed = (const float*)d_in[5];
    const float* emb  = (const float*)d_in[6];
    const float* Wih0 = (const float*)d_in[7];
    const float* Whh0 = (const float*)d_in[8];
    const float* bih0 = (const float*)d_in[9];
    const float* bhh0 = (const float*)d_in[10];
    const float* Wih1 = (const float*)d_in[11];
    const float* Whh1 = (const float*)d_in[12];
    const float* bih1 = (const float*)d_in[13];
    const float* bhh1 = (const float*)d_in[14];
    const float* Wa   = (const float*)d_in[15];
    const float* Wout = (const float*)d_in[16];
    float* dout = (float*)d_out;

    const int shmem = 13440 * 4;
    static int attr_set = 0;
    if (!attr_set){
        cudaFuncSetAttribute(kMain, cudaFuncAttributeMaxDynamicSharedMemorySize, shmem);
        attr_set = 1;
    }
    kMain<<<NB, NT, shmem>>>(toks, ctx, h0, c0, feed, emb,
                             Wih0, Whh0, bih0, bhh0,
                             Wih1, Whh1, bih1, bhh1,
                             Wa, Wout, dout);
}

// round 14
// speedup vs baseline: 1.1721x; 1.1721x over previous
#include <cuda_runtime.h>
#include <math.h>

// Problem constants
#define Bz 64
#define Hd 512
#define Sl 64
#define Tt 32
#define BH (Bz*Hd)
#define NB 128
#define NT 512

// Output layout
#define OFF_AT 1048576
#define OFF_HF 1179648
#define OFF_CF 1245184
#define OFF_FF 1310720

// ---------------------------------------------------------------------------
// Persistent storage.
__device__ float g_WT0[1536*2048];   // [emb|feed|h0] -> gates0, [k][j]
__device__ float g_WT1[1024*2048];   // [h0n|h1p]     -> gates1, [k][j]
__device__ float g_WoT[1024*512];    // Wout^T: [k(cvec|h1n)][j]
__device__ float g_ctxT[512*4096];   // ctx transposed [h][sb]
__device__ float g_ctxW[4096*512];   // [sb][k] = sum_j ctx[sb][j]*Wa[j][k]
__device__ float g_ctxWo[4096*512];  // [sb][j] = sum_k ctx[sb][k]*Wout[j][k] (k<512)
// Transposed activations [u][b]:
__device__ float g_h0T[Hd*Bz], g_h1T[Hd*Bz], g_feedT[Hd*Bz], g_embT[Hd*Bz];
__device__ float g_c1T[2][Hd*Bz];    // layer-1 cell state, ping-pong by t parity
// Split-K partials [j][b]:
__device__ float g_g0[8][2048*64];
__device__ float g_g1[8][2048*64];
__device__ float g_op[16][512*64];   // h1-half out partials
__device__ float g_opc[512*64];      // attention-half of out GEMM, [j][b]
__device__ unsigned g_arr[NB];       // per-block arrival flags (zero-init)
__device__ unsigned g_bargen = 0u;

__device__ __forceinline__ float sigf(float x){ return 1.0f/(1.0f+__expf(-x)); }

// Distributed-flag grid barrier (monotonic generations; no contended atomics).
__device__ __forceinline__ void gridbar_to(unsigned target){
    __syncthreads();
    if (blockIdx.x == 0){
        if (threadIdx.x > 0 && threadIdx.x < NB){
            unsigned g;
            do {
                asm volatile("ld.acquire.gpu.global.u32 %0, [%1];"
                             : "=r"(g) : "l"((const unsigned*)&g_arr[threadIdx.x]) : "memory");
            } while (g != target);
        }
        __syncthreads();
        if (threadIdx.x == 0)
            asm volatile("st.release.gpu.global.u32 [%0], %1;"
                         :: "l"(&g_bargen), "r"(target) : "memory");
    } else {
        if (threadIdx.x == 0){
            asm volatile("st.release.gpu.global.u32 [%0], %1;"
                         :: "l"(&g_arr[blockIdx.x]), "r"(target) : "memory");
            unsigned g;
            do {
                asm volatile("ld.acquire.gpu.global.u32 %0, [%1];"
                             : "=r"(g) : "l"((const unsigned*)&g_bargen) : "memory");
            } while (g != target);
        }
        __syncthreads();
    }
}

// ---------------------------------------------------------------------------
// 64b x 128j tile GEMM, 512 threads, 4b x 4j micro-tile (plain FFMA — the
// f32x2 variant measured slower). x rows [k][b], w rows [k][j]. Coalesced
// LDG, double-buffered smem, ONE __syncthreads per chunk.
// ---------------------------------------------------------------------------
template<bool XCG, class FX, class FW>
__device__ __forceinline__ void gemm_tile(float (&a)[4][4], FX fx, FW fw,
        int nch, int xpitch, int wpitch, float* sx, float* sw)
{
    const int tid = threadIdx.x;
    const int bq = tid & 15, kx = tid >> 4;
    const int jq = tid & 31, kw = tid >> 5;
    const int tb4 = (tid & 15) << 2, tj4 = (tid >> 4) << 2;
    float4 xv, wv0, wv1;
    {
        const float* xp = fx(0) + kx*xpitch + (bq<<2);
        xv  = XCG ? __ldcg((const float4*)xp) : __ldg((const float4*)xp);
        const float* wp = fw(0);
        wv0 = __ldg((const float4*)(wp + (size_t)kw*wpitch + (jq<<2)));
        wv1 = __ldg((const float4*)(wp + (size_t)(kw+16)*wpitch + (jq<<2)));
        *(float4*)(sx + kx*68 + (bq<<2))        = xv;
        *(float4*)(sw + kw*132 + (jq<<2))       = wv0;
        *(float4*)(sw + (kw+16)*132 + (jq<<2))  = wv1;
    }
    __syncthreads();

    for (int c = 0; c < nch; ++c){
        const bool more = (c+1 < nch);
        if (more){
            const float* xp = fx(c+1) + kx*xpitch + (bq<<2);
            xv  = XCG ? __ldcg((const float4*)xp) : __ldg((const float4*)xp);
            const float* wp = fw(c+1);
            wv0 = __ldg((const float4*)(wp + (size_t)kw*wpitch + (jq<<2)));
            wv1 = __ldg((const float4*)(wp + (size_t)(kw+16)*wpitch + (jq<<2)));
        }
        const float* xb = sx + (c&1)*2176;
        const float* wb = sw + (c&1)*4224;
        #pragma unroll
        for (int kk = 0; kk < 32; ++kk){
            float4 x4 = *(const float4*)(xb + kk*68 + tb4);
            float4 w4 = *(const float4*)(wb + kk*132 + tj4);
            a[0][0]=fmaf(x4.x,w4.x,a[0][0]); a[0][1]=fmaf(x4.x,w4.y,a[0][1]);
            a[0][2]=fmaf(x4.x,w4.z,a[0][2]); a[0][3]=fmaf(x4.x,w4.w,a[0][3]);
            a[1][0]=fmaf(x4.y,w4.x,a[1][0]); a[1][1]=fmaf(x4.y,w4.y,a[1][1]);
            a[1][2]=fmaf(x4.y,w4.z,a[1][2]); a[1][3]=fmaf(x4.y,w4.w,a[1][3]);
            a[2][0]=fmaf(x4.z,w4.x,a[2][0]); a[2][1]=fmaf(x4.z,w4.y,a[2][1]);
            a[2][2]=fmaf(x4.z,w4.z,a[2][2]); a[2][3]=fmaf(x4.z,w4.w,a[2][3]);
            a[3][0]=fmaf(x4.w,w4.x,a[3][0]); a[3][1]=fmaf(x4.w,w4.y,a[3][1]);
            a[3][2]=fmaf(x4.w,w4.z,a[3][2]); a[3][3]=fmaf(x4.w,w4.w,a[3][3]);
        }
        if (more){
            float* xn = sx + ((c+1)&1)*2176;
            float* wn = sw + ((c+1)&1)*4224;
            *(float4*)(xn + kx*68 + (bq<<2))        = xv;
            *(float4*)(wn + kw*132 + (jq<<2))       = wv0;
            *(float4*)(wn + (kw+16)*132 + (jq<<2))  = wv1;
        }
        __syncthreads();
    }
}

// ---------------------------------------------------------------------------
__global__ __launch_bounds__(NT, 1) void kMain(
    const int*   __restrict__ toks, const float* __restrict__ ctx,
    const float* __restrict__ h0i,  const float* __restrict__ c0i,
    const float* __restrict__ feedi,const float* __restrict__ emb,
    const float* __restrict__ Wih0, const float* __restrict__ Whh0,
    const float* __restrict__ bih0, const float* __restrict__ bhh0,
    const float* __restrict__ Wih1, const float* __restrict__ Whh1,
    const float* __restrict__ bih1, const float* __restrict__ bhh1,
    const float* __restrict__ Wa,   const float* __restrict__ Wout,
    float* __restrict__ dout)
{
    extern __shared__ float smem[];
    float* sx  = smem;                    // 2 x 32 x 68
    float* sw  = smem + 4352;             // 2 x 32 x 132
    float* qs  = smem + 4352 + 8448;      // 512
    float* sSc = qs + 512;                // 64
    float* sAl = sSc + 64;                // 64

    const int blk = blockIdx.x, tid = threadIdx.x;
    const int tb4 = (tid & 15) << 2, tj4 = (tid >> 4) << 2;

    unsigned bgen = *(volatile unsigned*)&g_bargen;

    // ---- per-thread persistent state ----
    float c0reg = 0.f, bs0i=0.f, bs0f=0.f, bs0g=0.f, bs0o=0.f;
    if (tid < 256){
        int elem = blk*256 + tid;         // = u*64 + b
        int u = elem >> 6, b = elem & 63;
        c0reg = c0i[b*Hd + u];
        bs0i = __ldg(bih0+u)      + __ldg(bhh0+u);
        bs0f = __ldg(bih0+512+u)  + __ldg(bhh0+512+u);
        bs0g = __ldg(bih0+1024+u) + __ldg(bhh0+1024+u);
        bs0o = __ldg(bih0+1536+u) + __ldg(bhh0+1536+u);
    }
    float bs1[4] = {0.f,0.f,0.f,0.f};     // biases for u = tid (S blocks)
    if (blk < Bz){
        #pragma unroll
        for (int g = 0; g < 4; ++g)
            bs1[g] = __ldg(bih1+g*512+tid) + __ldg(bhh1+g*512+tid);
    }

    // ---- init transposed state + c1 ping-pong + emb(t=0) ----
    if (tid < 256){
        int idx = blk*256 + tid;          // = b*512 + u
        int b = idx >> 9, u = idx & 511;
        __stcg(&g_h0T[u*64+b],  h0i[idx]);
        __stcg(&g_h1T[u*64+b],  h0i[BH + idx]);
        __stcg(&g_c1T[1][u*64+b], c0i[BH + idx]);
        __stcg(&g_feedT[u*64+b],feedi[idx]);
        __stcg(&g_embT[u*64+b], __ldg(emb + (size_t)__ldg(toks+b)*512 + u));
    }

    // ---- one-time transposes via smem 64x64 tiles ----
    {
        float* ts = sx;
        for (int tl = blk; tl < 1920; tl += NB){
            const float* sp; float* dp;
            int spitch, sk0, srow0, dpitch, dk0, dj0;
            if (tl < 768){
                int kt=tl>>5, jt=tl&31; dk0=kt<<6; dj0=jt<<6; srow0=dj0;
                dp=g_WT0; dpitch=2048;
                if (dk0<1024){ sp=Wih0; spitch=1024; sk0=dk0; }
                else         { sp=Whh0; spitch=512;  sk0=dk0-1024; }
            } else if (tl < 1280){
                int ti=tl-768; int kt=ti>>5, jt=ti&31; dk0=kt<<6; dj0=jt<<6; srow0=dj0;
                dp=g_WT1; dpitch=2048;
                if (dk0<512){ sp=Wih1; spitch=512; sk0=dk0; }
                else        { sp=Whh1; spitch=512; sk0=dk0-512; }
            } else if (tl < 1408){
                int ti=tl-1280; int kt=ti>>3, jt=ti&7; dk0=kt<<6; dj0=jt<<6; srow0=dj0;
                dp=g_WoT; dpitch=512; sp=Wout; spitch=1024; sk0=dk0;
            } else {
                int ti=tl-1408; int kt=ti>>6, jt=ti&63; dk0=kt<<6; dj0=jt<<6; srow0=dj0;
                dp=g_ctxT; dpitch=4096; sp=ctx; spitch=512; sk0=dk0;
            }
            #pragma unroll
            for (int it2=0; it2<2; ++it2){
                int q = it2*512 + tid; int jr=q>>4, kc4=(q&15)<<2;
                float4 v = __ldg((const float4*)(sp + (size_t)(srow0+jr)*spitch + sk0 + kc4));
                ts[(kc4+0)*65+jr]=v.x; ts[(kc4+1)*65+jr]=v.y;
                ts[(kc4+2)*65+jr]=v.z; ts[(kc4+3)*65+jr]=v.w;
            }
            __syncthreads();
            #pragma unroll
            for (int it2=0; it2<2; ++it2){
                int q = it2*512 + tid; int kr=q>>4, jc4=(q&15)<<2;
                float4 v = make_float4(ts[kr*65+jc4], ts[kr*65+jc4+1],
                                       ts[kr*65+jc4+2], ts[kr*65+jc4+3]);
                *(float4*)(dp + (size_t)(dk0+kr)*dpitch + dj0 + jc4) = v;
            }
            __syncthreads();
        }
    }
    gridbar_to(++bgen);

    // ---- one-time ctxW (Wa) and ctxWo (Wout cvec-half) ----
    for (int it = 0; it < 4; ++it){
        int job = it*NB + blk;            // 0..511
        int half = job >> 8;
        int j2 = job & 255;
        int sb0 = (j2 >> 2) << 6;
        int j0v = (j2 & 3) << 7;
        float a[4][4] = {};
        auto fx = [&](int c) -> const float* { return g_ctxT + (size_t)(c<<5)*4096 + sb0; };
        auto fw = [&](int c) -> const float* {
            return (half ? (const float*)g_WoT : Wa) + (size_t)(c<<5)*512 + j0v;
        };
        gemm_tile<false>(a, fx, fw, 16, 4096, 512, sx, sw);
        float* dst = half ? g_ctxWo : g_ctxW;
        #pragma unroll
        for (int bi = 0; bi < 4; ++bi)
            *(float4*)&dst[(size_t)(sb0 + tb4 + bi)*512 + j0v + tj4]
                = make_float4(a[bi][0],a[bi][1],a[bi][2],a[bi][3]);
    }
    gridbar_to(++bgen);

    // ---- time loop: 5 barriers/step ----
    for (int t = 0; t < Tt; ++t){

        // Phase A1: gates0 partials. 16 j-tiles(128) x 8 K-splits (K=192).
        {
            const int ks = blk >> 4, j0v = (blk & 15) << 7;
            const int kbase = ks * 192;
            float a[4][4] = {};
            auto fx = [&](int c) -> const float* {
                int kg = kbase + (c<<5);
                if (kg < 512)  return g_embT + kg*64;
                if (kg < 1024) return g_feedT + (kg-512)*64;
                return g_h0T + (kg-1024)*64;
            };
            auto fw = [&](int c) -> const float* {
                return g_WT0 + (size_t)(kbase + (c<<5))*2048 + j0v;
            };
            gemm_tile<true>(a, fx, fw, 6, 64, 2048, sx, sw);
            float* gp = g_g0[ks];
            #pragma unroll
            for (int jj = 0; jj < 4; ++jj)
                __stcg((float4*)&gp[(j0v + tj4 + jj)*64 + tb4],
                       make_float4(a[0][jj],a[1][jj],a[2][jj],a[3][jj]));
        }
        gridbar_to(++bgen);

        // Phase A2: combine + LSTM cell 0
        if (tid < 256){
            int elem = blk*256 + tid;
            int u = elem >> 6, b = elem & 63;
            float vi=bs0i, vf=bs0f, vg=bs0g, vo=bs0o;
            #pragma unroll
            for (int ks = 0; ks < 8; ++ks){
                const float* G = g_g0[ks];
                vi += __ldcg(&G[(u       )*64 + b]);
                vf += __ldcg(&G[(512+u)  *64 + b]);
                vg += __ldcg(&G[(1024+u) *64 + b]);
                vo += __ldcg(&G[(1536+u) *64 + b]);
            }
            float cn = sigf(vf)*c0reg + sigf(vi)*tanhf(vg);
            float hn = sigf(vo)*tanhf(cn);
            c0reg = cn;
            __stcg(&g_h0T[elem], hn);
            if (t == Tt-1){ dout[OFF_HF + b*Hd + u] = hn; dout[OFF_CF + b*Hd + u] = cn; }
        }
        gridbar_to(++bgen);

        // Phase B1: gates1 partials. 16 j-tiles x 8 K-splits (K=128).
        {
            const int ks = blk >> 4, j0v = (blk & 15) << 7;
            const int kbase = ks << 7;
            float a[4][4] = {};
            auto fx = [&](int c) -> const float* {
                int kg = kbase + (c<<5);
                return (kg < 512) ? g_h0T + kg*64 : g_h1T + (kg-512)*64;
            };
            auto fw = [&](int c) -> const float* {
                return g_WT1 + (size_t)(kbase + (c<<5))*2048 + j0v;
            };
            gemm_tile<true>(a, fx, fw, 4, 64, 2048, sx, sw);
            float* gp = g_g1[ks];
            #pragma unroll
            for (int jj = 0; jj < 4; ++jj)
                __stcg((float4*)&gp[(j0v + tj4 + jj)*64 + tb4],
                       make_float4(a[0][jj],a[1][jj],a[2][jj],a[3][jj]));
        }
        gridbar_to(++bgen);

        // Merged phase: blocks 0..63 -> S (cell1 + attention + attn-half out);
        //               blocks 64..127 -> O1 (redundant cell1 rows + h1-half out GEMM).
        const float* cprev = g_c1T[(t&1)^1];
        float* cnew = g_c1T[t&1];
        if (blk < Bz){
            const int b = blk, u = tid;
            float vi=bs1[0], vf=bs1[1], vg=bs1[2], vo=bs1[3];
            #pragma unroll
            for (int ks = 0; ks < 8; ++ks){
                const float* G = g_g1[ks];
                vi += __ldcg(&G[(u       )*64 + b]);
                vf += __ldcg(&G[(512+u)  *64 + b]);
                vg += __ldcg(&G[(1024+u) *64 + b]);
                vo += __ldcg(&G[(1536+u) *64 + b]);
            }
            float cn = sigf(vf)*__ldcg(&cprev[u*64 + b]) + sigf(vi)*tanhf(vg);
            float hn = sigf(vo)*tanhf(cn);
            qs[u] = hn;
            __syncthreads();
            // scores: warp wp -> s = wp*4..+3, lanes over k
            const int wp = tid >> 5, lane = tid & 31;
            #pragma unroll
            for (int si = 0; si < 4; ++si){
                const int s = wp*4 + si;
                const float* cw = g_ctxW + ((size_t)(s*Bz + b) << 9) + lane;
                float acc = 0.f;
                #pragma unroll
                for (int i = 0; i < 16; ++i) acc = fmaf(qs[lane + (i<<5)], __ldg(cw + (i<<5)), acc);
                #pragma unroll
                for (int o = 16; o; o >>= 1) acc += __shfl_xor_sync(0xffffffffu, acc, o);
                if (lane == 0) sSc[s] = acc;
            }
            __syncthreads();
            if (tid < 32){
                float v0 = sSc[tid], v1 = sSc[tid+32];
                float m = fmaxf(v0, v1);
                #pragma unroll
                for (int o = 16; o; o >>= 1) m = fmaxf(m, __shfl_xor_sync(0xffffffffu, m, o));
                float e0 = __expf(v0 - m), e1 = __expf(v1 - m);
                float ssum = e0 + e1;
                #pragma unroll
                for (int o = 16; o; o >>= 1) ssum += __shfl_xor_sync(0xffffffffu, ssum, o);
                float inv = 1.f/ssum;
                sAl[tid] = e0*inv;  sAl[tid+32] = e1*inv;
                dout[OFF_AT + t*Bz*Sl + b*Sl + tid]      = e0*inv;
                dout[OFF_AT + t*Bz*Sl + b*Sl + tid + 32] = e1*inv;
            }
            __syncthreads();
            {   // out_c[b][j] = sum_s al[s] * ctxWo[s*64+b][j], j = tid
                float acc = 0.f;
                const float* cw = g_ctxWo + ((size_t)b << 9) + tid;
                #pragma unroll 8
                for (int s2 = 0; s2 < Sl; ++s2)
                    acc = fmaf(sAl[s2], __ldg(cw + ((size_t)s2 << 15)), acc);
                __stcg(&g_opc[tid*64 + b], acc);
            }
        } else {
            // O1: ks = (blk-64)>>2 selects 32 u-rows; 4 j-tiles share a ks.
            const int ob = blk - 64;
            const int ks = ob >> 2, j0v = (ob & 3) << 7;
            const int kbase = ks << 5;
            const bool writer = (ob & 3) == 0;
            #pragma unroll
            for (int r = 0; r < 4; ++r){
                int ci = r*512 + tid;           // 0..2047
                int uo = ci >> 6, b = ci & 63, u = kbase + uo;
                float vi = __ldg(bih1+u)      + __ldg(bhh1+u);
                float vf = __ldg(bih1+512+u)  + __ldg(bhh1+512+u);
                float vg = __ldg(bih1+1024+u) + __ldg(bhh1+1024+u);
                float vo = __ldg(bih1+1536+u) + __ldg(bhh1+1536+u);
                #pragma unroll
                for (int p = 0; p < 8; ++p){
                    const float* G = g_g1[p];
                    vi += __ldcg(&G[(u       )*64 + b]);
                    vf += __ldcg(&G[(512+u)  *64 + b]);
                    vg += __ldcg(&G[(1024+u) *64 + b]);
                    vo += __ldcg(&G[(1536+u) *64 + b]);
                }
                float cn = sigf(vf)*__ldcg(&cprev[u*64 + b]) + sigf(vi)*tanhf(vg);
                float hn = sigf(vo)*tanhf(cn);
                sx[uo*68 + b] = hn;
                if (writer){
                    __stcg(&cnew[u*64 + b], cn);
                    __stcg(&g_h1T[u*64 + b], hn);
                    if (t == Tt-1){
                        dout[OFF_HF + BH + b*Hd + u] = hn;
                        dout[OFF_CF + BH + b*Hd + u] = cn;
                    }
                }
            }
            {   // stage w rows 512+kbase..+31, cols j0v..j0v+127
                const int jq = tid & 31, kw = tid >> 5;
                const float* wp = g_WoT + (size_t)(512 + kbase)*512 + j0v;
                float4 wv0 = __ldg((const float4*)(wp + (size_t)kw*512 + (jq<<2)));
                float4 wv1 = __ldg((const float4*)(wp + (size_t)(kw+16)*512 + (jq<<2)));
                *(float4*)(sw + kw*132 + (jq<<2))       = wv0;
                *(float4*)(sw + (kw+16)*132 + (jq<<2))  = wv1;
            }
            __syncthreads();
            float a[4][4] = {};
            #pragma unroll
            for (int kk = 0; kk < 32; ++kk){
                float4 x4 = *(const float4*)(sx + kk*68 + tb4);
                float4 w4 = *(const float4*)(sw + kk*132 + tj4);
                a[0][0]=fmaf(x4.x,w4.x,a[0][0]); a[0][1]=fmaf(x4.x,w4.y,a[0][1]);
                a[0][2]=fmaf(x4.x,w4.z,a[0][2]); a[0][3]=fmaf(x4.x,w4.w,a[0][3]);
                a[1][0]=fmaf(x4.y,w4.x,a[1][0]); a[1][1]=fmaf(x4.y,w4.y,a[1][1]);
                a[1][2]=fmaf(x4.y,w4.z,a[1][2]); a[1][3]=fmaf(x4.y,w4.w,a[1][3]);
                a[2][0]=fmaf(x4.z,w4.x,a[2][0]); a[2][1]=fmaf(x4.z,w4.y,a[2][1]);
                a[2][2]=fmaf(x4.z,w4.z,a[2][2]); a[2][3]=fmaf(x4.z,w4.w,a[2][3]);
                a[3][0]=fmaf(x4.w,w4.x,a[3][0]); a[3][1]=fmaf(x4.w,w4.y,a[3][1]);
                a[3][2]=fmaf(x4.w,w4.z,a[3][2]); a[3][3]=fmaf(x4.w,w4.w,a[3][3]);
            }
            float* gp = g_op[ks];
            #pragma unroll
            for (int jj = 0; jj < 4; ++jj)
                __stcg((float4*)&gp[(j0v + tj4 + jj)*64 + tb4],
                       make_float4(a[0][jj],a[1][jj],a[2][jj],a[3][jj]));
            __syncthreads();   // keep sx/sw stable until all warps done
        }
        gridbar_to(++bgen);

        // Phase O2: opc + 16 partials + tanh -> feedT, outputs[t], feedf;
        // gather emb for step t+1.
        if (tid < 256){
            int elem = blk*256 + tid;     // = h*64 + b
            int h = elem >> 6, b = elem & 63;
            float s = __ldcg(&g_opc[elem]);
            #pragma unroll
            for (int ks = 0; ks < 16; ++ks) s += __ldcg(&g_op[ks][elem]);
            float o = tanhf(s);
            __stcg(&g_feedT[elem], o);
            dout[t*BH + b*Hd + h] = o;
            if (t == Tt-1) dout[OFF_FF + b*Hd + h] = o;
            if (t+1 < Tt){
                int b2 = elem >> 9, k2 = elem & 511;
                float ev = __ldg(emb + (size_t)__ldg(toks + (t+1)*Bz + b2)*512 + k2);
                __stcg(&g_embT[k2*64 + b2], ev);
            }
        }
        gridbar_to(++bgen);
    }
}

// ---------------------------------------------------------------------------
extern "C" void kernel_launch(void* const* d_in, const int* in_sizes, int n_in,
                              void* d_out, int out_size)
{
    const int*   toks = (const int*)  d_in[0];
    // d_in[1] = src (unused by the reference computation)
    const float* ctx  = (const float*)d_in[2];
    const float* h0   = (const float*)d_in[3];
    const float* c0   = (const float*)d_in[4];
    const float* feed = (const float*)d_in[5];
    const float* emb  = (const float*)d_in[6];
    const float* Wih0 = (const float*)d_in[7];
    const float* Whh0 = (const float*)d_in[8];
    const float* bih0 = (const float*)d_in[9];
    const float* bhh0 = (const float*)d_in[10];
    const float* Wih1 = (const float*)d_in[11];
    const float* Whh1 = (const float*)d_in[12];
    const float* bih1 = (const float*)d_in[13];
    const float* bhh1 = (const float*)d_in[14];
    const float* Wa   = (const float*)d_in[15];
    const float* Wout = (const float*)d_in[16];
    float* dout = (float*)d_out;

    const int shmem = 13440 * 4;
    static int attr_set = 0;
    if (!attr_set){
        cudaFuncSetAttribute(kMain, cudaFuncAttributeMaxDynamicSharedMemorySize, shmem);
        attr_set = 1;
    }
    kMain<<<NB, NT, shmem>>>(toks, ctx, h0, c0, feed, emb,
                             Wih0, Whh0, bih0, bhh0,
                             Wih1, Whh1, bih1, bhh1,
                             Wa, Wout, dout);
}

// round 16
// speedup vs baseline: 1.3083x; 1.1162x over previous
#include <cuda_runtime.h>
#include <cuda_bf16.h>
#include <mma.h>
#include <math.h>
#include <stdint.h>

using namespace nvcuda;

#define Bz 64
#define Hd 512
#define Sl 64
#define Tt 32
#define BH (Bz*Hd)
#define NB 128
#define NT 512

#define OFF_AT 1048576
#define OFF_HF 1179648
#define OFF_CF 1245184
#define OFF_FF 1310720

// ---------------------------------------------------------------------------
// Persistent storage.
// Per-block pre-packed bf16 weight tiles, [tile][128j][72k] (padded pitch 72):
__device__ unsigned short gW0h[384*9216], gW0l[384*9216];  // A1: 128 blk x 3 chunks
__device__ unsigned short gW1h[256*9216], gW1l[256*9216];  // B1: 128 blk x 2 chunks
__device__ float g_WoT[1024*512];    // Wout^T [k][j]
__device__ float g_ctxT[512*4096];   // ctx transposed [h][sb]
__device__ float g_ctxW[4096*512];   // [sb][k] = sum_j ctx[sb][j]*Wa[j][k]
__device__ float g_ctxWo[4096*512];  // [sb][j] (cvec-half of Wout, pre-applied)
// packed bf16 hi|lo<<16 activation images, [b][512]:
__device__ unsigned g_ih0[BH], g_ih1[BH], g_ifeed[BH], g_iemb[BH];
__device__ float g_c1T[2][Hd*Bz];
__device__ float g_g0[8][2048*64];
__device__ float g_g1[8][2048*64];
__device__ float g_op[16][512*64];
__device__ float g_opc[512*64];
__device__ unsigned g_arr[NB];
__device__ unsigned g_bargen = 0u;

__device__ __forceinline__ float sigf(float x){ return 1.0f/(1.0f+__expf(-x)); }

__device__ __forceinline__ unsigned packbf(float v){
    unsigned short h = __bfloat16_as_ushort(__float2bfloat16(v));
    float hv = __bfloat162float(__ushort_as_bfloat16(h));
    unsigned short l = __bfloat16_as_ushort(__float2bfloat16(v - hv));
    return (unsigned)h | ((unsigned)l << 16);
}

__device__ __forceinline__ void gridbar_to(unsigned target){
    __syncthreads();
    if (blockIdx.x == 0){
        if (threadIdx.x > 0 && threadIdx.x < NB){
            unsigned g;
            do { asm volatile("ld.acquire.gpu.global.u32 %0, [%1];"
                 : "=r"(g) : "l"((const unsigned*)&g_arr[threadIdx.x]) : "memory"); } while (g != target);
        }
        __syncthreads();
        if (threadIdx.x == 0)
            asm volatile("st.release.gpu.global.u32 [%0], %1;" :: "l"(&g_bargen), "r"(target) : "memory");
    } else {
        if (threadIdx.x == 0){
            asm volatile("st.release.gpu.global.u32 [%0], %1;" :: "l"(&g_arr[blockIdx.x]), "r"(target) : "memory");
            unsigned g;
            do { asm volatile("ld.acquire.gpu.global.u32 %0, [%1];"
                 : "=r"(g) : "l"((const unsigned*)&g_bargen) : "memory"); } while (g != target);
        }
        __syncthreads();
    }
}

// ---------------------------------------------------------------------------
// SIMT 64x128 tile GEMM (one-time ctxW/ctxWo precompute + merged-phase O1).
template<bool XCG, class FX, class FW>
__device__ __forceinline__ void gemm_tile(float (&a)[4][4], FX fx, FW fw,
        int nch, int xpitch, int wpitch, float* sx, float* sw)
{
    const int tid = threadIdx.x;
    const int bq = tid & 15, kx = tid >> 4;
    const int jq = tid & 31, kw = tid >> 5;
    const int tb4 = (tid & 15) << 2, tj4 = (tid >> 4) << 2;
    float4 xv, wv0, wv1;
    {
        const float* xp = fx(0) + kx*xpitch + (bq<<2);
        xv  = XCG ? __ldcg((const float4*)xp) : __ldg((const float4*)xp);
        const float* wp = fw(0);
        wv0 = __ldg((const float4*)(wp + (size_t)kw*wpitch + (jq<<2)));
        wv1 = __ldg((const float4*)(wp + (size_t)(kw+16)*wpitch + (jq<<2)));
        *(float4*)(sx + kx*68 + (bq<<2))        = xv;
        *(float4*)(sw + kw*132 + (jq<<2))       = wv0;
        *(float4*)(sw + (kw+16)*132 + (jq<<2))  = wv1;
    }
    __syncthreads();
    for (int c = 0; c < nch; ++c){
        const bool more = (c+1 < nch);
        if (more){
            const float* xp = fx(c+1) + kx*xpitch + (bq<<2);
            xv  = XCG ? __ldcg((const float4*)xp) : __ldg((const float4*)xp);
            const float* wp = fw(c+1);
            wv0 = __ldg((const float4*)(wp + (size_t)kw*wpitch + (jq<<2)));
            wv1 = __ldg((const float4*)(wp + (size_t)(kw+16)*wpitch + (jq<<2)));
        }
        const float* xb = sx + (c&1)*2176;
        const float* wb = sw + (c&1)*4224;
        #pragma unroll
        for (int kk = 0; kk < 32; ++kk){
            float4 x4 = *(const float4*)(xb + kk*68 + tb4);
            float4 w4 = *(const float4*)(wb + kk*132 + tj4);
            a[0][0]=fmaf(x4.x,w4.x,a[0][0]); a[0][1]=fmaf(x4.x,w4.y,a[0][1]);
            a[0][2]=fmaf(x4.x,w4.z,a[0][2]); a[0][3]=fmaf(x4.x,w4.w,a[0][3]);
            a[1][0]=fmaf(x4.y,w4.x,a[1][0]); a[1][1]=fmaf(x4.y,w4.y,a[1][1]);
            a[1][2]=fmaf(x4.y,w4.z,a[1][2]); a[1][3]=fmaf(x4.y,w4.w,a[1][3]);
            a[2][0]=fmaf(x4.z,w4.x,a[2][0]); a[2][1]=fmaf(x4.z,w4.y,a[2][1]);
            a[2][2]=fmaf(x4.z,w4.z,a[2][2]); a[2][3]=fmaf(x4.z,w4.w,a[2][3]);
            a[3][0]=fmaf(x4.w,w4.x,a[3][0]); a[3][1]=fmaf(x4.w,w4.y,a[3][1]);
            a[3][2]=fmaf(x4.w,w4.z,a[3][2]); a[3][3]=fmaf(x4.w,w4.w,a[3][3]);
        }
        if (more){
            float* xn = sx + ((c+1)&1)*2176;
            float* wn = sw + ((c+1)&1)*4224;
            *(float4*)(xn + kx*68 + (bq<<2))        = xv;
            *(float4*)(wn + kw*132 + (jq<<2))       = wv0;
            *(float4*)(wn + (kw+16)*132 + (jq<<2))  = wv1;
        }
        __syncthreads();
    }
}

// ---------------------------------------------------------------------------
__global__ __launch_bounds__(NT, 1) void kMain(
    const int*   __restrict__ toks, const float* __restrict__ ctx,
    const float* __restrict__ h0i,  const float* __restrict__ c0i,
    const float* __restrict__ feedi,const float* __restrict__ emb,
    const float* __restrict__ Wih0, const float* __restrict__ Whh0,
    const float* __restrict__ bih0, const float* __restrict__ bhh0,
    const float* __restrict__ Wih1, const float* __restrict__ Whh1,
    const float* __restrict__ bih1, const float* __restrict__ bhh1,
    const float* __restrict__ Wa,   const float* __restrict__ Wout,
    float* __restrict__ dout)
{
    extern __shared__ __align__(16) char smemc[];
    // wmma tiles (aliased with sx/sw: used in disjoint phases)
    char* sWh_c = smemc;                    // 18432 B  [128j][72k] bf16 hi
    char* sWl_c = smemc + 18432;            // 18432 B  lo
    char* sBh_c = smemc + 36864;            // 9216 B   [64b][72k] bf16 hi
    char* sBl_c = smemc + 46080;            // 9216 B   lo          (end 55296)
    float* sx  = (float*)smemc;             // 4352 floats (aliases sW)
    float* sw  = sx + 4352;                 // 8448 floats
    float* qs  = (float*)(smemc + 55296);   // 512
    float* sSc = qs + 512;                  // 64
    float* sAl = sSc + 64;                  // 64

    const int blk = blockIdx.x, tid = threadIdx.x;
    const int wid = tid >> 5;
    const int tb4 = (tid & 15) << 2, tj4 = (tid >> 4) << 2;

    unsigned bgen = *(volatile unsigned*)&g_bargen;

    // ---- per-thread persistent state ----
    float c0reg = 0.f, bs0i=0.f, bs0f=0.f, bs0g=0.f, bs0o=0.f;
    if (tid < 256){
        int elem = blk*256 + tid;         // = u*64 + b
        int u = elem >> 6, b = elem & 63;
        c0reg = c0i[b*Hd + u];
        bs0i = __ldg(bih0+u)      + __ldg(bhh0+u);
        bs0f = __ldg(bih0+512+u)  + __ldg(bhh0+512+u);
        bs0g = __ldg(bih0+1024+u) + __ldg(bhh0+1024+u);
        bs0o = __ldg(bih0+1536+u) + __ldg(bhh0+1536+u);
    }
    float bs1[4] = {0.f,0.f,0.f,0.f};
    if (blk < Bz){
        #pragma unroll
        for (int g = 0; g < 4; ++g)
            bs1[g] = __ldg(bih1+g*512+tid) + __ldg(bhh1+g*512+tid);
    }

    // ---- init: packed activation images (idx = b*512+u) + c1 ----
    if (tid < 256){
        int idx = blk*256 + tid;
        int b = idx >> 9, u = idx & 511;
        __stcg(&g_ih0[idx],  packbf(h0i[idx]));
        __stcg(&g_ih1[idx],  packbf(h0i[BH + idx]));
        __stcg(&g_ifeed[idx],packbf(feedi[idx]));
        __stcg(&g_iemb[idx], packbf(__ldg(emb + (size_t)__ldg(toks+b)*512 + u)));
        __stcg(&g_c1T[1][u*64 + b], c0i[BH + idx]);
    }

    // ---- one-time: per-block weight tiles -> padded bf16 hi/lo ----
    {
        const int ks0 = blk >> 4, jt0 = blk & 15;
        for (int tp = 0; tp < 5; ++tp){
            const bool isb1 = tp >= 3;
            const int c = isb1 ? tp-3 : tp;
            unsigned short* dh = isb1 ? gW1h + (size_t)(blk*2+c)*9216 : gW0h + (size_t)(blk*3+c)*9216;
            unsigned short* dl = isb1 ? gW1l + (size_t)(blk*2+c)*9216 : gW0l + (size_t)(blk*3+c)*9216;
            for (int i = tid; i < 8192; i += NT){
                int j = i >> 6, k = i & 63;
                int jg = jt0*128 + j;
                float v;
                if (!isb1){
                    int kg = ks0*192 + c*64 + k;
                    v = (kg < 1024) ? __ldg(&Wih0[(size_t)jg*1024 + kg])
                                    : __ldg(&Whh0[(size_t)jg*512 + kg-1024]);
                } else {
                    int kg = ks0*128 + c*64 + k;
                    v = (kg < 512) ? __ldg(&Wih1[(size_t)jg*512 + kg])
                                   : __ldg(&Whh1[(size_t)jg*512 + kg-512]);
                }
                unsigned p = packbf(v);
                dh[j*72 + k] = (unsigned short)(p & 0xFFFFu);
                dl[j*72 + k] = (unsigned short)(p >> 16);
            }
        }
    }

    // ---- one-time transposes: WoT (128 tiles) + ctxT (512 tiles) ----
    {
        float* ts = sx;
        for (int tl = blk; tl < 640; tl += NB){
            const float* sp; float* dp;
            int spitch, sk0, srow0, dpitch, dk0, dj0;
            if (tl < 128){
                int kt=tl>>3, jt2=tl&7; dk0=kt<<6; dj0=jt2<<6; srow0=dj0;
                dp=g_WoT; dpitch=512; sp=Wout; spitch=1024; sk0=dk0;
            } else {
                int ti=tl-128; int kt=ti>>6, jt2=ti&63; dk0=kt<<6; dj0=jt2<<6; srow0=dj0;
                dp=g_ctxT; dpitch=4096; sp=ctx; spitch=512; sk0=dk0;
            }
            #pragma unroll
            for (int it2=0; it2<2; ++it2){
                int q = it2*512 + tid; int jr=q>>4, kc4=(q&15)<<2;
                float4 v = __ldg((const float4*)(sp + (size_t)(srow0+jr)*spitch + sk0 + kc4));
                ts[(kc4+0)*65+jr]=v.x; ts[(kc4+1)*65+jr]=v.y;
                ts[(kc4+2)*65+jr]=v.z; ts[(kc4+3)*65+jr]=v.w;
            }
            __syncthreads();
            #pragma unroll
            for (int it2=0; it2<2; ++it2){
                int q = it2*512 + tid; int kr=q>>4, jc4=(q&15)<<2;
                float4 v = make_float4(ts[kr*65+jc4], ts[kr*65+jc4+1],
                                       ts[kr*65+jc4+2], ts[kr*65+jc4+3]);
                *(float4*)(dp + (size_t)(dk0+kr)*dpitch + dj0 + jc4) = v;
            }
            __syncthreads();
        }
    }
    gridbar_to(++bgen);

    // ---- one-time ctxW (Wa) and ctxWo (Wout cvec-half) ----
    for (int it = 0; it < 4; ++it){
        int job = it*NB + blk;
        int half = job >> 8;
        int j2 = job & 255;
        int sb0 = (j2 >> 2) << 6;
        int j0v = (j2 & 3) << 7;
        float a[4][4] = {};
        auto fx = [&](int c) -> const float* { return g_ctxT + (size_t)(c<<5)*4096 + sb0; };
        auto fw = [&](int c) -> const float* {
            return (half ? (const float*)g_WoT : Wa) + (size_t)(c<<5)*512 + j0v;
        };
        gemm_tile<false>(a, fx, fw, 16, 4096, 512, sx, sw);
        float* dst = half ? g_ctxWo : g_ctxW;
        #pragma unroll
        for (int bi = 0; bi < 4; ++bi)
            *(float4*)&dst[(size_t)(sb0 + tb4 + bi)*512 + j0v + tj4]
                = make_float4(a[bi][0],a[bi][1],a[bi][2],a[bi][3]);
    }
    gridbar_to(++bgen);

    const int wj = wid >> 2, wb = wid & 3;  // wmma: 4 j-groups(32) x 4 b-groups(16)
    const __nv_bfloat16* Ahp = (const __nv_bfloat16*)sWh_c + wj*32*72;
    const __nv_bfloat16* Alp = (const __nv_bfloat16*)sWl_c + wj*32*72;
    const __nv_bfloat16* Bhp = (const __nv_bfloat16*)sBh_c + wb*16*72;
    const __nv_bfloat16* Blp = (const __nv_bfloat16*)sBl_c + wb*16*72;

    // ---- time loop: 5 barriers/step ----
    for (int t = 0; t < Tt; ++t){

        // Phase A1 (wmma): gates0. block = (ks of K=192, jt of 128 j).
        {
            const int ks = blk >> 4, j0v = (blk & 15) << 7;
            wmma::fragment<wmma::accumulator, 16,16,16, float> c0f, c1f;
            wmma::fill_fragment(c0f, 0.0f);
            wmma::fill_fragment(c1f, 0.0f);
            #pragma unroll
            for (int c = 0; c < 3; ++c){
                const uint4* tAh = (const uint4*)(gW0h + (size_t)(blk*3+c)*9216);
                const uint4* tAl = (const uint4*)(gW0l + (size_t)(blk*3+c)*9216);
                for (int i = tid; i < 1152; i += NT){
                    ((uint4*)sWh_c)[i] = __ldg(tAh + i);
                    ((uint4*)sWl_c)[i] = __ldg(tAl + i);
                }
                const int kbase = ks*192 + (c<<6);
                const unsigned* img = (kbase < 512) ? g_iemb + kbase
                                    : (kbase < 1024) ? g_ifeed + (kbase-512)
                                    : g_ih0 + (kbase-1024);
                {
                    const int b = tid >> 3, kq = (tid & 7) << 3;
                    uint4 p0 = __ldcg((const uint4*)(img + b*512 + kq));
                    uint4 p1 = __ldcg((const uint4*)(img + b*512 + kq + 4));
                    uint4 hh, ll;
                    hh.x = (p0.x & 0xFFFFu) | (p0.y << 16);
                    hh.y = (p0.z & 0xFFFFu) | (p0.w << 16);
                    hh.z = (p1.x & 0xFFFFu) | (p1.y << 16);
                    hh.w = (p1.z & 0xFFFFu) | (p1.w << 16);
                    ll.x = (p0.x >> 16) | (p0.y & 0xFFFF0000u);
                    ll.y = (p0.z >> 16) | (p0.w & 0xFFFF0000u);
                    ll.z = (p1.x >> 16) | (p1.y & 0xFFFF0000u);
                    ll.w = (p1.z >> 16) | (p1.w & 0xFFFF0000u);
                    *(uint4*)(sBh_c + b*144 + kq*2) = hh;
                    *(uint4*)(sBl_c + b*144 + kq*2) = ll;
                }
                __syncthreads();
                #pragma unroll
                for (int kk = 0; kk < 64; kk += 16){
                    wmma::fragment<wmma::matrix_a, 16,16,16, __nv_bfloat16, wmma::row_major> ah0, ah1, al0, al1;
                    wmma::fragment<wmma::matrix_b, 16,16,16, __nv_bfloat16, wmma::col_major> bh, bl;
                    wmma::load_matrix_sync(ah0, Ahp + kk, 72);
                    wmma::load_matrix_sync(ah1, Ahp + 16*72 + kk, 72);
                    wmma::load_matrix_sync(al0, Alp + kk, 72);
                    wmma::load_matrix_sync(al1, Alp + 16*72 + kk, 72);
                    wmma::load_matrix_sync(bh,  Bhp + kk, 72);
                    wmma::load_matrix_sync(bl,  Blp + kk, 72);
                    wmma::mma_sync(c0f, ah0, bh, c0f);
                    wmma::mma_sync(c0f, ah0, bl, c0f);
                    wmma::mma_sync(c0f, al0, bh, c0f);
                    wmma::mma_sync(c1f, ah1, bh, c1f);
                    wmma::mma_sync(c1f, ah1, bl, c1f);
                    wmma::mma_sync(c1f, al1, bh, c1f);
                }
                __syncthreads();
            }
            float* gp = g_g0[ks] + (size_t)(j0v + wj*32)*64 + wb*16;
            wmma::store_matrix_sync(gp, c0f, 64, wmma::mem_row_major);
            wmma::store_matrix_sync(gp + 16*64, c1f, 64, wmma::mem_row_major);
        }
        gridbar_to(++bgen);

        // Phase A2: combine + LSTM cell 0
        if (tid < 256){
            int elem = blk*256 + tid;
            int u = elem >> 6, b = elem & 63;
            float vi=bs0i, vf=bs0f, vg=bs0g, vo=bs0o;
            #pragma unroll
            for (int ks = 0; ks < 8; ++ks){
                const float* G = g_g0[ks];
                vi += __ldcg(&G[(u       )*64 + b]);
                vf += __ldcg(&G[(512+u)  *64 + b]);
                vg += __ldcg(&G[(1024+u) *64 + b]);
                vo += __ldcg(&G[(1536+u) *64 + b]);
            }
            float cn = sigf(vf)*c0reg + sigf(vi)*tanhf(vg);
            float hn = sigf(vo)*tanhf(cn);
            c0reg = cn;
            __stcg(&g_ih0[b*512 + u], packbf(hn));
            if (t == Tt-1){ dout[OFF_HF + b*Hd + u] = hn; dout[OFF_CF + b*Hd + u] = cn; }
        }
        gridbar_to(++bgen);

        // Phase B1 (wmma): gates1. K=128 per block, 2 chunks.
        {
            const int ks = blk >> 4, j0v = (blk & 15) << 7;
            wmma::fragment<wmma::accumulator, 16,16,16, float> c0f, c1f;
            wmma::fill_fragment(c0f, 0.0f);
            wmma::fill_fragment(c1f, 0.0f);
            #pragma unroll
            for (int c = 0; c < 2; ++c){
                const uint4* tAh = (const uint4*)(gW1h + (size_t)(blk*2+c)*9216);
                const uint4* tAl = (const uint4*)(gW1l + (size_t)(blk*2+c)*9216);
                for (int i = tid; i < 1152; i += NT){
                    ((uint4*)sWh_c)[i] = __ldg(tAh + i);
                    ((uint4*)sWl_c)[i] = __ldg(tAl + i);
                }
                const int kbase = (ks << 7) + (c<<6);
                const unsigned* img = (kbase < 512) ? g_ih0 + kbase : g_ih1 + (kbase-512);
                {
                    const int b = tid >> 3, kq = (tid & 7) << 3;
                    uint4 p0 = __ldcg((const uint4*)(img + b*512 + kq));
                    uint4 p1 = __ldcg((const uint4*)(img + b*512 + kq + 4));
                    uint4 hh, ll;
                    hh.x = (p0.x & 0xFFFFu) | (p0.y << 16);
                    hh.y = (p0.z & 0xFFFFu) | (p0.w << 16);
                    hh.z = (p1.x & 0xFFFFu) | (p1.y << 16);
                    hh.w = (p1.z & 0xFFFFu) | (p1.w << 16);
                    ll.x = (p0.x >> 16) | (p0.y & 0xFFFF0000u);
                    ll.y = (p0.z >> 16) | (p0.w & 0xFFFF0000u);
                    ll.z = (p1.x >> 16) | (p1.y & 0xFFFF0000u);
                    ll.w = (p1.z >> 16) | (p1.w & 0xFFFF0000u);
                    *(uint4*)(sBh_c + b*144 + kq*2) = hh;
                    *(uint4*)(sBl_c + b*144 + kq*2) = ll;
                }
                __syncthreads();
                #pragma unroll
                for (int kk = 0; kk < 64; kk += 16){
                    wmma::fragment<wmma::matrix_a, 16,16,16, __nv_bfloat16, wmma::row_major> ah0, ah1, al0, al1;
                    wmma::fragment<wmma::matrix_b, 16,16,16, __nv_bfloat16, wmma::col_major> bh, bl;
                    wmma::load_matrix_sync(ah0, Ahp + kk, 72);
                    wmma::load_matrix_sync(ah1, Ahp + 16*72 + kk, 72);
                    wmma::load_matrix_sync(al0, Alp + kk, 72);
                    wmma::load_matrix_sync(al1, Alp + 16*72 + kk, 72);
                    wmma::load_matrix_sync(bh,  Bhp + kk, 72);
                    wmma::load_matrix_sync(bl,  Blp + kk, 72);
                    wmma::mma_sync(c0f, ah0, bh, c0f);
                    wmma::mma_sync(c0f, ah0, bl, c0f);
                    wmma::mma_sync(c0f, al0, bh, c0f);
                    wmma::mma_sync(c1f, ah1, bh, c1f);
                    wmma::mma_sync(c1f, ah1, bl, c1f);
                    wmma::mma_sync(c1f, al1, bh, c1f);
                }
                __syncthreads();
            }
            float* gp = g_g1[ks] + (size_t)(j0v + wj*32)*64 + wb*16;
            wmma::store_matrix_sync(gp, c0f, 64, wmma::mem_row_major);
            wmma::store_matrix_sync(gp + 16*64, c1f, 64, wmma::mem_row_major);
        }
        gridbar_to(++bgen);

        // Merged phase: blocks 0..63 -> S; blocks 64..127 -> O1.
        const float* cprev = g_c1T[(t&1)^1];
        float* cnew = g_c1T[t&1];
        if (blk < Bz){
            const int b = blk, u = tid;
            float vi=bs1[0], vf=bs1[1], vg=bs1[2], vo=bs1[3];
            #pragma unroll
            for (int ks = 0; ks < 8; ++ks){
                const float* G = g_g1[ks];
                vi += __ldcg(&G[(u       )*64 + b]);
                vf += __ldcg(&G[(512+u)  *64 + b]);
                vg += __ldcg(&G[(1024+u) *64 + b]);
                vo += __ldcg(&G[(1536+u) *64 + b]);
            }
            float cn = sigf(vf)*__ldcg(&cprev[u*64 + b]) + sigf(vi)*tanhf(vg);
            float hn = sigf(vo)*tanhf(cn);
            qs[u] = hn;
            __syncthreads();
            const int wp = tid >> 5, lane = tid & 31;
            #pragma unroll
            for (int si = 0; si < 4; ++si){
                const int s = wp*4 + si;
                const float* cw = g_ctxW + ((size_t)(s*Bz + b) << 9) + lane;
                float acc = 0.f;
                #pragma unroll
                for (int i = 0; i < 16; ++i) acc = fmaf(qs[lane + (i<<5)], __ldg(cw + (i<<5)), acc);
                #pragma unroll
                for (int o = 16; o; o >>= 1) acc += __shfl_xor_sync(0xffffffffu, acc, o);
                if (lane == 0) sSc[s] = acc;
            }
            __syncthreads();
            if (tid < 32){
                float v0 = sSc[tid], v1 = sSc[tid+32];
                float m = fmaxf(v0, v1);
                #pragma unroll
                for (int o = 16; o; o >>= 1) m = fmaxf(m, __shfl_xor_sync(0xffffffffu, m, o));
                float e0 = __expf(v0 - m), e1 = __expf(v1 - m);
                float ssum = e0 + e1;
                #pragma unroll
                for (int o = 16; o; o >>= 1) ssum += __shfl_xor_sync(0xffffffffu, ssum, o);
                float inv = 1.f/ssum;
                sAl[tid] = e0*inv;  sAl[tid+32] = e1*inv;
                dout[OFF_AT + t*Bz*Sl + b*Sl + tid]      = e0*inv;
                dout[OFF_AT + t*Bz*Sl + b*Sl + tid + 32] = e1*inv;
            }
            __syncthreads();
            {
                float acc = 0.f;
                const float* cw = g_ctxWo + ((size_t)b << 9) + tid;
                #pragma unroll 8
                for (int s2 = 0; s2 < Sl; ++s2)
                    acc = fmaf(sAl[s2], __ldg(cw + ((size_t)s2 << 15)), acc);
                __stcg(&g_opc[tid*64 + b], acc);
            }
        } else {
            const int ob = blk - 64;
            const int ks = ob >> 2, j0v = (ob & 3) << 7;
            const int kbase = ks << 5;
            const bool writer = (ob & 3) == 0;
            #pragma unroll
            for (int r = 0; r < 4; ++r){
                int ci = r*512 + tid;
                int uo = ci >> 6, b = ci & 63, u = kbase + uo;
                float vi = __ldg(bih1+u)      + __ldg(bhh1+u);
                float vf = __ldg(bih1+512+u)  + __ldg(bhh1+512+u);
                float vg = __ldg(bih1+1024+u) + __ldg(bhh1+1024+u);
                float vo = __ldg(bih1+1536+u) + __ldg(bhh1+1536+u);
                #pragma unroll
                for (int p = 0; p < 8; ++p){
                    const float* G = g_g1[p];
                    vi += __ldcg(&G[(u       )*64 + b]);
                    vf += __ldcg(&G[(512+u)  *64 + b]);
                    vg += __ldcg(&G[(1024+u) *64 + b]);
                    vo += __ldcg(&G[(1536+u) *64 + b]);
                }
                float cn = sigf(vf)*__ldcg(&cprev[u*64 + b]) + sigf(vi)*tanhf(vg);
                float hn = sigf(vo)*tanhf(cn);
                sx[uo*68 + b] = hn;
                if (writer){
                    __stcg(&cnew[u*64 + b], cn);
                    __stcg(&g_ih1[b*512 + u], packbf(hn));
                    if (t == Tt-1){
                        dout[OFF_HF + BH + b*Hd + u] = hn;
                        dout[OFF_CF + BH + b*Hd + u] = cn;
                    }
                }
            }
            {
                const int jq = tid & 31, kw = tid >> 5;
                const float* wp = g_WoT + (size_t)(512 + kbase)*512 + j0v;
                float4 wv0 = __ldg((const float4*)(wp + (size_t)kw*512 + (jq<<2)));
                float4 wv1 = __ldg((const float4*)(wp + (size_t)(kw+16)*512 + (jq<<2)));
                *(float4*)(sw + kw*132 + (jq<<2))       = wv0;
                *(float4*)(sw + (kw+16)*132 + (jq<<2))  = wv1;
            }
            __syncthreads();
            float a[4][4] = {};
            #pragma unroll
            for (int kk = 0; kk < 32; ++kk){
                float4 x4 = *(const float4*)(sx + kk*68 + tb4);
                float4 w4 = *(const float4*)(sw + kk*132 + tj4);
                a[0][0]=fmaf(x4.x,w4.x,a[0][0]); a[0][1]=fmaf(x4.x,w4.y,a[0][1]);
                a[0][2]=fmaf(x4.x,w4.z,a[0][2]); a[0][3]=fmaf(x4.x,w4.w,a[0][3]);
                a[1][0]=fmaf(x4.y,w4.x,a[1][0]); a[1][1]=fmaf(x4.y,w4.y,a[1][1]);
                a[1][2]=fmaf(x4.y,w4.z,a[1][2]); a[1][3]=fmaf(x4.y,w4.w,a[1][3]);
                a[2][0]=fmaf(x4.z,w4.x,a[2][0]); a[2][1]=fmaf(x4.z,w4.y,a[2][1]);
                a[2][2]=fmaf(x4.z,w4.z,a[2][2]); a[2][3]=fmaf(x4.z,w4.w,a[2][3]);
                a[3][0]=fmaf(x4.w,w4.x,a[3][0]); a[3][1]=fmaf(x4.w,w4.y,a[3][1]);
                a[3][2]=fmaf(x4.w,w4.z,a[3][2]); a[3][3]=fmaf(x4.w,w4.w,a[3][3]);
            }
            float* gp = g_op[ks];
            #pragma unroll
            for (int jj = 0; jj < 4; ++jj)
                __stcg((float4*)&gp[(j0v + tj4 + jj)*64 + tb4],
                       make_float4(a[0][jj],a[1][jj],a[2][jj],a[3][jj]));
            __syncthreads();
        }
        gridbar_to(++bgen);

        // Phase O2: combine + tanh -> feed image, outputs[t], feedf; emb(t+1).
        if (tid < 256){
            int elem = blk*256 + tid;     // = h*64 + b
            int h = elem >> 6, b = elem & 63;
            float s = __ldcg(&g_opc[elem]);
            #pragma unroll
            for (int ks = 0; ks < 16; ++ks) s += __ldcg(&g_op[ks][elem]);
            float o = tanhf(s);
            __stcg(&g_ifeed[b*512 + h], packbf(o));
            dout[t*BH + b*Hd + h] = o;
            if (t == Tt-1) dout[OFF_FF + b*Hd + h] = o;
            if (t+1 < Tt){
                int b2 = elem >> 9, k2 = elem & 511;
                float ev = __ldg(emb + (size_t)__ldg(toks + (t+1)*Bz + b2)*512 + k2);
                __stcg(&g_iemb[elem], packbf(ev));
            }
        }
        gridbar_to(++bgen);
    }
}

// ---------------------------------------------------------------------------
extern "C" void kernel_launch(void* const* d_in, const int* in_sizes, int n_in,
                              void* d_out, int out_size)
{
    const int*   toks = (const int*)  d_in[0];
    const float* ctx  = (const float*)d_in[2];
    const float* h0   = (const float*)d_in[3];
    const float* c0   = (const float*)d_in[4];
    const float* feed = (const float*)d_in[5];
    const float* emb  = (const float*)d_in[6];
    const float* Wih0 = (const float*)d_in[7];
    const float* Whh0 = (const float*)d_in[8];
    const float* bih0 = (const float*)d_in[9];
    const float* bhh0 = (const float*)d_in[10];
    const float* Wih1 = (const float*)d_in[11];
    const float* Whh1 = (const float*)d_in[12];
    const float* bih1 = (const float*)d_in[13];
    const float* bhh1 = (const float*)d_in[14];
    const float* Wa   = (const float*)d_in[15];
    const float* Wout = (const float*)d_in[16];
    float* dout = (float*)d_out;

    const int shmem = 55296 + (512 + 64 + 64) * 4;   // 57856 B
    static int attr_set = 0;
    if (!attr_set){
        cudaFuncSetAttribute(kMain, cudaFuncAttributeMaxDynamicSharedMemorySize, shmem);
        attr_set = 1;
    }
    kMain<<<NB, NT, shmem>>>(toks, ctx, h0, c0, feed, emb,
                             Wih0, Whh0, bih0, bhh0,
                             Wih1, Whh1, bih1, bhh1,
                             Wa, Wout, dout);
}